// round 3
// baseline (speedup 1.0000x reference)
#include <cuda_runtime.h>
#include <cuda_bf16.h>
#include <cstdint>
#include <cstddef>

// Problem constants
#define BATCH 8
#define SEQ   512
#define NTOK  4096      // BATCH*SEQ
#define EMB   1024
#define E3    3072
#define NHEAD 16
#define HDIM  64
#define HID   4096
#define ODIM  128
#define NLAYER 8

// ---------------------------------------------------------------------------
// Scratch (device globals; allocation is forbidden)
// ---------------------------------------------------------------------------
__device__ float g_z   [(size_t)NTOK * EMB];   // 16 MB (fp32 residual stream)
__device__ float g_qkv [(size_t)NTOK * E3];    // 48 MB
__device__ float g_tmp [(size_t)NTOK * EMB];   // 16 MB (attn-proj / ffn2 out)
__device__ float g_M   [ODIM * ODIM];
__device__ float g_aug [ODIM * 2 * ODIM];
__device__ float g_P   [ODIM * EMB];

// split planes (bf16 hi/lo)
#define WTOT ((size_t)NLAYER*E3*EMB + (size_t)NLAYER*EMB*EMB + \
              2*(size_t)NLAYER*HID*EMB + (size_t)ODIM*EMB)
__device__ __nv_bfloat16 g_wh[WTOT];
__device__ __nv_bfloat16 g_wl[WTOT];
__device__ __nv_bfloat16 g_zh[(size_t)NTOK * EMB];
__device__ __nv_bfloat16 g_zl[(size_t)NTOK * EMB];
__device__ __nv_bfloat16 g_ah[(size_t)NTOK * EMB];
__device__ __nv_bfloat16 g_al[(size_t)NTOK * EMB];
__device__ __nv_bfloat16 g_hh[(size_t)NTOK * HID];
__device__ __nv_bfloat16 g_hl[(size_t)NTOK * HID];

// ---------------------------------------------------------------------------
// helpers
// ---------------------------------------------------------------------------
__device__ __forceinline__ void split2v(float x, float y,
                                        __nv_bfloat162& h, __nv_bfloat162& l)
{
    h = __floats2bfloat162_rn(x, y);
    float rx = x - __bfloat162float(h.x);
    float ry = y - __bfloat162float(h.y);
    l = __floats2bfloat162_rn(rx, ry);
}

__device__ __forceinline__ void ldmatrix4(uint32_t addr, uint32_t& r0, uint32_t& r1,
                                          uint32_t& r2, uint32_t& r3)
{
    asm volatile("ldmatrix.sync.aligned.m8n8.x4.shared.b16 {%0,%1,%2,%3}, [%4];"
                 : "=r"(r0), "=r"(r1), "=r"(r2), "=r"(r3) : "r"(addr));
}

__device__ __forceinline__ void mma16816(float* c, uint32_t a0, uint32_t a1,
                                         uint32_t a2, uint32_t a3,
                                         uint32_t b0, uint32_t b1)
{
    asm volatile("mma.sync.aligned.m16n8k16.row.col.f32.bf16.bf16.f32 "
                 "{%0,%1,%2,%3},{%4,%5,%6,%7},{%8,%9},{%0,%1,%2,%3};"
                 : "+f"(c[0]), "+f"(c[1]), "+f"(c[2]), "+f"(c[3])
                 : "r"(a0), "r"(a1), "r"(a2), "r"(a3), "r"(b0), "r"(b1));
}

__device__ __forceinline__ void cpasync16(uint32_t s, const void* g)
{
    asm volatile("cp.async.cg.shared.global [%0], [%1], 16;" :: "r"(s), "l"(g));
}

// ===========================================================================
// Weight pre-split: fp32 -> bf16 hi/lo planes
// ===========================================================================
__global__ void __launch_bounds__(256) wsplit_kernel(const float4* __restrict__ w,
                                                     __nv_bfloat16* __restrict__ hi,
                                                     __nv_bfloat16* __restrict__ lo,
                                                     int n4)
{
    int i = blockIdx.x * 256 + threadIdx.x;
    if (i >= n4) return;
    float4 v = w[i];
    __nv_bfloat162 h0, l0, h1, l1;
    split2v(v.x, v.y, h0, l0);
    split2v(v.z, v.w, h1, l1);
    *(__nv_bfloat162*)(hi + (size_t)i * 4)     = h0;
    *(__nv_bfloat162*)(hi + (size_t)i * 4 + 2) = h1;
    *(__nv_bfloat162*)(lo + (size_t)i * 4)     = l0;
    *(__nv_bfloat162*)(lo + (size_t)i * 4 + 2) = l1;
}

// ===========================================================================
// Tensor-core GEMM v3: C[M,N] = A[M,K]*B[N,K]^T, split-bf16 operands from
// global planes, cp.async feed, 2-stage, 2 CTAs/SM.
// op: 0 = fp32 out, 1 = fp32 out + bias, 2 = bias + relu -> split bf16 out only
// ===========================================================================
#define TBM 128
#define TBN 128
#define TBK 32
#define RW  20                  // words per row: 16 data (32 bf16) + 4 pad
#define PLANE  (128 * RW)       // 2560 words
#define STAGEW (4 * PLANE)      // 10240 words (40 KB)
#define TC_SMEM (2 * STAGEW * 4)

__global__ void __launch_bounds__(256, 2) gemm_tc_kernel(
    const __nv_bfloat16* __restrict__ Ah, const __nv_bfloat16* __restrict__ Al,
    const __nv_bfloat16* __restrict__ Bh, const __nv_bfloat16* __restrict__ Bl,
    const float* __restrict__ bias, float* __restrict__ C,
    __nv_bfloat16* __restrict__ Ch, __nv_bfloat16* __restrict__ Cl,
    int M, int N, int K, int op)
{
    extern __shared__ uint32_t sm[];
    const uint32_t sbase = (uint32_t)__cvta_generic_to_shared(sm);

    const int tid = threadIdx.x;
    const int lane = tid & 31;
    const int wid = tid >> 5;
    const int wm = wid >> 2;
    const int wn = wid & 3;
    const int bm = blockIdx.y * TBM;
    const int bn = blockIdx.x * TBN;

    float acc[4][4][4];
#pragma unroll
    for (int i = 0; i < 4; i++)
#pragma unroll
        for (int j = 0; j < 4; j++)
#pragma unroll
            for (int r = 0; r < 4; r++) acc[i][j][r] = 0.f;

    // cp.async mapping: 2048 16B chunks per stage, 8 per thread.
    // idx -> plane(0:Ah 1:Al 2:Bh 3:Bl), row 0..127, chunk 0..3
    const __nv_bfloat16* gsrc[8];
    uint32_t soff[8];
#pragma unroll
    for (int i = 0; i < 8; i++) {
        int idx = tid + i * 256;
        int pl = idx >> 9;
        int r  = (idx >> 2) & 127;
        int c  = idx & 3;
        const __nv_bfloat16* base =
            (pl == 0) ? Ah + (size_t)(bm + r) * K :
            (pl == 1) ? Al + (size_t)(bm + r) * K :
            (pl == 2) ? Bh + (size_t)(bn + r) * K :
                        Bl + (size_t)(bn + r) * K;
        gsrc[i] = base + c * 8;
        soff[i] = 4u * (uint32_t)(pl * PLANE + r * RW + c * 4);
    }

    const int T = K / TBK;

    // prologue: stage 0
#pragma unroll
    for (int i = 0; i < 8; i++) cpasync16(sbase + soff[i], gsrc[i]);
    asm volatile("cp.async.commit_group;");

    // ldmatrix lane addressing
    const int arow = wm * 64 + (lane & 7) + ((lane & 8) ? 8 : 0);
    const int akw0 = (lane & 16) ? 4 : 0;
    const int brow = wn * 32 + (lane & 7) + ((lane & 16) ? 8 : 0);
    const int bkw0 = (lane & 8) ? 4 : 0;

    for (int t = 0; t < T; t++) {
        if (t + 1 < T) {
            const uint32_t sb = sbase + (uint32_t)(((t + 1) & 1) * STAGEW) * 4u;
            const int k0 = (t + 1) * TBK;
#pragma unroll
            for (int i = 0; i < 8; i++) cpasync16(sb + soff[i], gsrc[i] + k0);
            asm volatile("cp.async.commit_group;");
            asm volatile("cp.async.wait_group 1;");
        } else {
            asm volatile("cp.async.wait_group 0;");
        }
        __syncthreads();

        const uint32_t bufb = sbase + (uint32_t)((t & 1) * STAGEW) * 4u;
#pragma unroll
        for (int ks = 0; ks < 2; ks++) {
            const int akw = ks * 8 + akw0;
            const int bkw = ks * 8 + bkw0;
            uint32_t bh[4][2], bl[4][2];
#pragma unroll
            for (int np = 0; np < 2; np++) {
                uint32_t r0, r1, r2, r3;
                ldmatrix4(bufb + 4u * (2 * PLANE + (brow + np * 16) * RW + bkw),
                          r0, r1, r2, r3);
                bh[2 * np][0] = r0; bh[2 * np][1] = r1;
                bh[2 * np + 1][0] = r2; bh[2 * np + 1][1] = r3;
                ldmatrix4(bufb + 4u * (3 * PLANE + (brow + np * 16) * RW + bkw),
                          r0, r1, r2, r3);
                bl[2 * np][0] = r0; bl[2 * np][1] = r1;
                bl[2 * np + 1][0] = r2; bl[2 * np + 1][1] = r3;
            }
#pragma unroll
            for (int mt = 0; mt < 4; mt++) {
                uint32_t a0, a1, a2, a3, e0, e1, e2, e3;
                ldmatrix4(bufb + 4u * (0 * PLANE + (arow + mt * 16) * RW + akw),
                          a0, a1, a2, a3);
                ldmatrix4(bufb + 4u * (1 * PLANE + (arow + mt * 16) * RW + akw),
                          e0, e1, e2, e3);
#pragma unroll
                for (int nt = 0; nt < 4; nt++) {
                    float* c = acc[mt][nt];
                    mma16816(c, a0, a1, a2, a3, bh[nt][0], bh[nt][1]);
                    mma16816(c, a0, a1, a2, a3, bl[nt][0], bl[nt][1]);
                    mma16816(c, e0, e1, e2, e3, bh[nt][0], bh[nt][1]);
                }
            }
        }
        __syncthreads();
    }

    // ---- epilogue ----
#pragma unroll
    for (int mt = 0; mt < 4; mt++) {
        const int row = bm + wm * 64 + mt * 16 + (lane >> 2);
#pragma unroll
        for (int nt = 0; nt < 4; nt++) {
            const int col = bn + wn * 32 + nt * 8 + 2 * (lane & 3);
            float b0 = 0.f, b1 = 0.f;
            if (op >= 1) { b0 = bias[col]; b1 = bias[col + 1]; }
            float v0 = acc[mt][nt][0] + b0;
            float v1 = acc[mt][nt][1] + b1;
            float v2 = acc[mt][nt][2] + b0;
            float v3 = acc[mt][nt][3] + b1;
            if (op == 2) {
                v0 = fmaxf(v0, 0.f); v1 = fmaxf(v1, 0.f);
                v2 = fmaxf(v2, 0.f); v3 = fmaxf(v3, 0.f);
                __nv_bfloat162 h0, l0, h1, l1;
                split2v(v0, v1, h0, l0);
                split2v(v2, v3, h1, l1);
                size_t o0 = (size_t)row * N + col;
                size_t o1 = (size_t)(row + 8) * N + col;
                *(__nv_bfloat162*)(Ch + o0) = h0;
                *(__nv_bfloat162*)(Cl + o0) = l0;
                *(__nv_bfloat162*)(Ch + o1) = h1;
                *(__nv_bfloat162*)(Cl + o1) = l1;
            } else {
                *(float2*)(C + (size_t)row * N + col) = make_float2(v0, v1);
                *(float2*)(C + (size_t)(row + 8) * N + col) = make_float2(v2, v3);
            }
        }
    }
}

// ---------------------------------------------------------------------------
// fp32 GEMM (only for the 128x128 normal-equations matrix)
// ---------------------------------------------------------------------------
__global__ void __launch_bounds__(256) gemm_f32_kernel(
    const float* __restrict__ A, const float* __restrict__ B,
    float* __restrict__ C, int M, int N, int K)
{
    __shared__ float As[32][132];
    __shared__ float Bs[32][132];

    const int bm = blockIdx.y * 128;
    const int bn = blockIdx.x * 128;
    const int tid = threadIdx.x;
    const int tm = (tid >> 4) << 3;
    const int tn = (tid & 15) << 3;

    float acc[8][8];
#pragma unroll
    for (int i = 0; i < 8; i++)
#pragma unroll
        for (int j = 0; j < 8; j++) acc[i][j] = 0.f;

    for (int k0 = 0; k0 < K; k0 += 32) {
#pragma unroll
        for (int i = 0; i < 4; i++) {
            int idx = tid + i * 256;
            int row = idx >> 3;
            int col = (idx & 7) << 2;
            float4 a = *(const float4*)(A + (size_t)(bm + row) * K + k0 + col);
            As[col + 0][row] = a.x; As[col + 1][row] = a.y;
            As[col + 2][row] = a.z; As[col + 3][row] = a.w;
            float4 b = *(const float4*)(B + (size_t)(bn + row) * K + k0 + col);
            Bs[col + 0][row] = b.x; Bs[col + 1][row] = b.y;
            Bs[col + 2][row] = b.z; Bs[col + 3][row] = b.w;
        }
        __syncthreads();
#pragma unroll
        for (int kk = 0; kk < 32; kk++) {
            float av[8], bv[8];
#pragma unroll
            for (int i = 0; i < 8; i++) { av[i] = As[kk][tm + i]; bv[i] = Bs[kk][tn + i]; }
#pragma unroll
            for (int i = 0; i < 8; i++)
#pragma unroll
                for (int j = 0; j < 8; j++)
                    acc[i][j] += av[i] * bv[j];
        }
        __syncthreads();
    }
#pragma unroll
    for (int i = 0; i < 8; i++)
#pragma unroll
        for (int j = 0; j < 8; j++)
            C[(size_t)(bm + tm + i) * N + bn + tn + j] = acc[i][j];
}

// ---------------------------------------------------------------------------
// Gauss-Jordan inverse of SPD 128x128 g_M -> right half of g_aug
// ---------------------------------------------------------------------------
__global__ void __launch_bounds__(256) gj_kernel()
{
    const int tid = threadIdx.x;
    for (int idx = tid; idx < ODIM * 2 * ODIM; idx += 256) {
        int r = idx >> 8, c = idx & 255;
        g_aug[idx] = (c < ODIM) ? g_M[r * ODIM + c] : ((c - ODIM) == r ? 1.f : 0.f);
    }
    __syncthreads();

    const int r = tid >> 1;
    const int cb = (tid & 1) << 7;
    for (int k = 0; k < ODIM; k++) {
        float ip = 1.f / g_aug[k * 256 + k];
        __syncthreads();
        g_aug[k * 256 + tid] *= ip;
        __syncthreads();
        float f = (r != k) ? g_aug[r * 256 + k] : 0.f;
        __syncthreads();
        const float* prow = &g_aug[k * 256 + cb];
        float* rrow = &g_aug[r * 256 + cb];
#pragma unroll 8
        for (int c = 0; c < 128; c++) rrow[c] -= f * prow[c];
        __syncthreads();
    }
}

// P[o][e] = sum_j Minv[o][j] * W_obs[j][e]
__global__ void __launch_bounds__(256) pmat_kernel(const float* __restrict__ W)
{
    const int o = blockIdx.y;
    const int e = blockIdx.x * 256 + threadIdx.x;
    __shared__ float smv[ODIM];
    if (threadIdx.x < ODIM) smv[threadIdx.x] = g_aug[o * 256 + ODIM + threadIdx.x];
    __syncthreads();
    float acc = 0.f;
#pragma unroll 8
    for (int j = 0; j < ODIM; j++) acc += smv[j] * W[(size_t)j * EMB + e];
    g_P[(size_t)o * EMB + e] = acc;
}

// z[t][e] = sum_o x[t][o] * P[o][e] + PE(s,e); writes fp32 z + split planes
__global__ void __launch_bounds__(256) embed_kernel(const float* __restrict__ x)
{
    const int t = blockIdx.x;
    const int s = t & (SEQ - 1);
    __shared__ float sx[ODIM];
    if (threadIdx.x < ODIM) sx[threadIdx.x] = x[(size_t)t * ODIM + threadIdx.x];
    __syncthreads();
    float acc[4] = {0.f, 0.f, 0.f, 0.f};
#pragma unroll 4
    for (int o = 0; o < ODIM; o++) {
        float xv = sx[o];
        const float* pr = g_P + (size_t)o * EMB + threadIdx.x;
#pragma unroll
        for (int c = 0; c < 4; c++) acc[c] += xv * pr[c * 256];
    }
    const float kln = 9.210340371976184f / 1024.0f;
#pragma unroll
    for (int c = 0; c < 4; c++) {
        int e = threadIdx.x + c * 256;
        float freq = expf(-(float)(e & ~1) * kln);
        float arg = (float)s * freq;
        float pe = (e & 1) ? cosf(arg) : sinf(arg);
        float v = acc[c] + pe;
        size_t off = (size_t)t * EMB + e;
        g_z[off] = v;
        __nv_bfloat16 hv = __float2bfloat16_rn(v);
        g_zh[off] = hv;
        g_zl[off] = __float2bfloat16_rn(v - __bfloat162float(hv));
    }
}

// ---------------------------------------------------------------------------
// Attention: 8 warps per block = 8 queries of one (b,h); split-plane output
// ---------------------------------------------------------------------------
__global__ void __launch_bounds__(256) attn_kernel(const float* __restrict__ qkv,
                                                   __nv_bfloat16* __restrict__ oh,
                                                   __nv_bfloat16* __restrict__ ol)
{
    const int w = threadIdx.x >> 5, lane = threadIdx.x & 31;
    const int bh = blockIdx.x >> 6;
    const int qg = blockIdx.x & 63;
    const int b = bh >> 4, hd = bh & 15;
    const int s = qg * 8 + w;

    __shared__ float sq[8][64];
    __shared__ float sp[8][512];
    __shared__ float st[32][68];

    const float* base = qkv + (size_t)(b * SEQ) * E3 + hd * (3 * HDIM);
    {
        const float* qp = base + (size_t)s * E3;
        sq[w][lane] = qp[lane];
        sq[w][lane + 32] = qp[lane + 32];
    }

    for (int u0 = 0; u0 < SEQ; u0 += 32) {
        __syncthreads();
#pragma unroll
        for (int i = 0; i < 2; i++) {
            int idx = threadIdx.x + i * 256;
            int r = idx >> 4, c4 = (idx & 15) << 2;
            float4 kk = *(const float4*)(base + (size_t)(u0 + r) * E3 + HDIM + c4);
            *(float4*)(&st[r][c4]) = kk;
        }
        __syncthreads();
        float dot = 0.f;
#pragma unroll
        for (int d = 0; d < 64; d += 4) {
            float4 kk = *(const float4*)(&st[lane][d]);
            dot += kk.x * sq[w][d] + kk.y * sq[w][d + 1]
                 + kk.z * sq[w][d + 2] + kk.w * sq[w][d + 3];
        }
        sp[w][u0 + lane] = dot * 0.125f;
    }
    __syncthreads();

    float mx = -1e30f;
#pragma unroll
    for (int i = 0; i < 16; i++) mx = fmaxf(mx, sp[w][lane + i * 32]);
#pragma unroll
    for (int o = 16; o; o >>= 1) mx = fmaxf(mx, __shfl_xor_sync(0xffffffffu, mx, o));
    float sum = 0.f;
#pragma unroll
    for (int i = 0; i < 16; i++) {
        float p = __expf(sp[w][lane + i * 32] - mx);
        sp[w][lane + i * 32] = p;
        sum += p;
    }
#pragma unroll
    for (int o = 16; o; o >>= 1) sum += __shfl_xor_sync(0xffffffffu, sum, o);
    const float inv = 1.f / sum;

    float a0 = 0.f, a1 = 0.f;
    for (int u0 = 0; u0 < SEQ; u0 += 32) {
        __syncthreads();
#pragma unroll
        for (int i = 0; i < 2; i++) {
            int idx = threadIdx.x + i * 256;
            int r = idx >> 4, c4 = (idx & 15) << 2;
            float4 vv = *(const float4*)(base + (size_t)(u0 + r) * E3 + 2 * HDIM + c4);
            *(float4*)(&st[r][c4]) = vv;
        }
        __syncthreads();
#pragma unroll 8
        for (int u = 0; u < 32; u++) {
            float p = sp[w][u0 + u];
            float2 vv = *(const float2*)&st[u][2 * lane];
            a0 += p * vv.x;
            a1 += p * vv.y;
        }
    }
    const int t = b * SEQ + s;
    float v0 = a0 * inv, v1 = a1 * inv;
    __nv_bfloat162 hv, lv;
    split2v(v0, v1, hv, lv);
    size_t off = (size_t)t * EMB + hd * HDIM + 2 * lane;
    *(__nv_bfloat162*)(oh + off) = hv;
    *(__nv_bfloat162*)(ol + off) = lv;
}

// ---------------------------------------------------------------------------
// Fused residual + LayerNorm; writes fp32 z + split planes
// ---------------------------------------------------------------------------
__device__ __forceinline__ float block_sum256(float v, float* sbuf)
{
#pragma unroll
    for (int o = 16; o; o >>= 1) v += __shfl_xor_sync(0xffffffffu, v, o);
    if ((threadIdx.x & 31) == 0) sbuf[threadIdx.x >> 5] = v;
    __syncthreads();
    float tot = 0.f;
#pragma unroll
    for (int i = 0; i < 8; i++) tot += sbuf[i];
    return tot;
}

__global__ void __launch_bounds__(256) ln_kernel(float* __restrict__ z,
                                                 const float* __restrict__ add,
                                                 const float* __restrict__ g,
                                                 const float* __restrict__ b,
                                                 __nv_bfloat16* __restrict__ zh,
                                                 __nv_bfloat16* __restrict__ zl)
{
    __shared__ float red[16];
    const size_t t = blockIdx.x;
    float* zp = z + t * EMB;
    const float* ap = add + t * EMB;

    float v[4];
    float s = 0.f;
#pragma unroll
    for (int i = 0; i < 4; i++) {
        int e = threadIdx.x + i * 256;
        v[i] = zp[e] + ap[e];
        s += v[i];
    }
    float mean = block_sum256(s, red) * (1.f / 1024.f);
    float q = 0.f;
#pragma unroll
    for (int i = 0; i < 4; i++) { float d = v[i] - mean; q += d * d; }
    float var = block_sum256(q, red + 8) * (1.f / 1024.f);
    float rstd = rsqrtf(var + 1e-5f);
#pragma unroll
    for (int i = 0; i < 4; i++) {
        int e = threadIdx.x + i * 256;
        float o = (v[i] - mean) * rstd * g[e] + b[e];
        zp[e] = o;
        __nv_bfloat16 hv = __float2bfloat16_rn(o);
        zh[t * EMB + e] = hv;
        zl[t * EMB + e] = __float2bfloat16_rn(o - __bfloat162float(hv));
    }
}

// ---------------------------------------------------------------------------
// Launch
// ---------------------------------------------------------------------------
extern "C" void kernel_launch(void* const* d_in, const int* in_sizes, int n_in,
                              void* d_out, int out_size)
{
    const float* x     = (const float*)d_in[0];
    const float* W_obs = (const float*)d_in[1];
    const float* Wqkv  = (const float*)d_in[2];
    const float* Wo    = (const float*)d_in[3];
    const float* bo    = (const float*)d_in[4];
    const float* ln1g  = (const float*)d_in[5];
    const float* ln1b  = (const float*)d_in[6];
    const float* W1    = (const float*)d_in[7];
    const float* b1    = (const float*)d_in[8];
    const float* W2    = (const float*)d_in[9];
    const float* b2    = (const float*)d_in[10];
    const float* ln2g  = (const float*)d_in[11];
    const float* ln2b  = (const float*)d_in[12];
    float* out = (float*)d_out;

    float *z, *qkvb, *tmpb, *Mb;
    __nv_bfloat16 *wh, *wl, *zh, *zl, *ah, *al, *hh, *hl;
    cudaGetSymbolAddress((void**)&z,    g_z);
    cudaGetSymbolAddress((void**)&qkvb, g_qkv);
    cudaGetSymbolAddress((void**)&tmpb, g_tmp);
    cudaGetSymbolAddress((void**)&Mb,   g_M);
    cudaGetSymbolAddress((void**)&wh,   g_wh);
    cudaGetSymbolAddress((void**)&wl,   g_wl);
    cudaGetSymbolAddress((void**)&zh,   g_zh);
    cudaGetSymbolAddress((void**)&zl,   g_zl);
    cudaGetSymbolAddress((void**)&ah,   g_ah);
    cudaGetSymbolAddress((void**)&al,   g_al);
    cudaGetSymbolAddress((void**)&hh,   g_hh);
    cudaGetSymbolAddress((void**)&hl,   g_hl);

    cudaFuncSetAttribute(gemm_tc_kernel,
                         cudaFuncAttributeMaxDynamicSharedMemorySize, TC_SMEM);

    // split-plane offsets
    const size_t OQKV = 0;
    const size_t OO   = OQKV + (size_t)NLAYER * E3 * EMB;
    const size_t OW1  = OO   + (size_t)NLAYER * EMB * EMB;
    const size_t OW2  = OW1  + (size_t)NLAYER * HID * EMB;
    const size_t OOBS = OW2  + (size_t)NLAYER * EMB * HID;

    // --- weight pre-split ---
    {
        int n4;
        n4 = (int)((size_t)NLAYER * E3 * EMB / 4);
        wsplit_kernel<<<(n4 + 255) / 256, 256>>>((const float4*)Wqkv, wh + OQKV, wl + OQKV, n4);
        n4 = (int)((size_t)NLAYER * EMB * EMB / 4);
        wsplit_kernel<<<(n4 + 255) / 256, 256>>>((const float4*)Wo, wh + OO, wl + OO, n4);
        n4 = (int)((size_t)NLAYER * HID * EMB / 4);
        wsplit_kernel<<<(n4 + 255) / 256, 256>>>((const float4*)W1, wh + OW1, wl + OW1, n4);
        n4 = (int)((size_t)NLAYER * EMB * HID / 4);
        wsplit_kernel<<<(n4 + 255) / 256, 256>>>((const float4*)W2, wh + OW2, wl + OW2, n4);
        n4 = ODIM * EMB / 4;
        wsplit_kernel<<<(n4 + 255) / 256, 256>>>((const float4*)W_obs, wh + OOBS, wl + OOBS, n4);
    }

    // --- embed: pinv via normal equations (fp32 for conditioning) ---
    gemm_f32_kernel<<<dim3(1, 1), 256>>>(W_obs, W_obs, Mb, ODIM, ODIM, EMB);
    gj_kernel<<<1, 256>>>();
    pmat_kernel<<<dim3(EMB / 256, ODIM), 256>>>(W_obs);
    embed_kernel<<<NTOK, 256>>>(x);

    for (int l = 0; l < NLAYER; l++) {
        const __nv_bfloat16* qh = wh + OQKV + (size_t)l * E3 * EMB;
        const __nv_bfloat16* ql = wl + OQKV + (size_t)l * E3 * EMB;
        const __nv_bfloat16* oh = wh + OO + (size_t)l * EMB * EMB;
        const __nv_bfloat16* ol = wl + OO + (size_t)l * EMB * EMB;
        const __nv_bfloat16* w1h = wh + OW1 + (size_t)l * HID * EMB;
        const __nv_bfloat16* w1l = wl + OW1 + (size_t)l * HID * EMB;
        const __nv_bfloat16* w2h = wh + OW2 + (size_t)l * EMB * HID;
        const __nv_bfloat16* w2l = wl + OW2 + (size_t)l * EMB * HID;

        gemm_tc_kernel<<<dim3(E3 / TBN, NTOK / TBM), 256, TC_SMEM>>>(
            zh, zl, qh, ql, nullptr, qkvb, nullptr, nullptr, NTOK, E3, EMB, 0);
        attn_kernel<<<BATCH * NHEAD * (SEQ / 8), 256>>>(qkvb, ah, al);
        gemm_tc_kernel<<<dim3(EMB / TBN, NTOK / TBM), 256, TC_SMEM>>>(
            ah, al, oh, ol, bo + l * EMB, tmpb, nullptr, nullptr, NTOK, EMB, EMB, 1);
        ln_kernel<<<NTOK, 256>>>(z, tmpb, ln1g + l * EMB, ln1b + l * EMB, zh, zl);
        gemm_tc_kernel<<<dim3(HID / TBN, NTOK / TBM), 256, TC_SMEM>>>(
            zh, zl, w1h, w1l, b1 + l * HID, nullptr, hh, hl, NTOK, HID, EMB, 2);
        gemm_tc_kernel<<<dim3(EMB / TBN, NTOK / TBM), 256, TC_SMEM>>>(
            hh, hl, w2h, w2l, b2 + l * EMB, tmpb, nullptr, nullptr, NTOK, EMB, HID, 1);
        ln_kernel<<<NTOK, 256>>>(z, tmpb, ln2g + l * EMB, ln2b + l * EMB, zh, zl);
    }

    // --- readout: x_hat = z @ W_obs^T ---
    gemm_tc_kernel<<<dim3(ODIM / TBN, NTOK / TBM), 256, TC_SMEM>>>(
        zh, zl, wh + OOBS, wl + OOBS, nullptr, out, nullptr, nullptr,
        NTOK, ODIM, EMB, 0);
}